// round 10
// baseline (speedup 1.0000x reference)
#include <cuda_runtime.h>
#include <cuda_fp16.h>
#include <math.h>
#include <stdint.h>

// Problem constants
#define BB 16
#define NN_TOK 1024
#define DD 384
#define C2 768
#define C4 1536
#define HEADS 8
#define HD 48
#define T_TOK (BB*NN_TOK)      // 16384
#define T2 (2*T_TOK)           // 32768 (both streams)

// ---------------- scratch (device globals; no allocation allowed) -------------
__device__ float  g_x[(size_t)T2*DD];              // packed x1 || x2 (fp32, residual)
__device__ __half g_ln[(size_t)T2*DD];             // ln1 outputs (half, GEMM A)
__device__ __half g_lnw[(size_t)T_TOK*C2];         // ln2 output (half, GEMM A)
__device__ float  g_qkv[(size_t)T2*1152];
__device__ float  g_qn[(size_t)2*BB*HEADS*HD*NN_TOK];
__device__ float  g_kn[(size_t)2*BB*HEADS*HD*NN_TOK];
__device__ float  g_attnp[(size_t)8*2*BB*HEADS*HD*HD];
__device__ float  g_attn[(size_t)2*BB*HEADS*HD*HD];
__device__ __half g_attnout[(size_t)T2*DD];        // half (GEMM A)
__device__ float  g_ch[(size_t)T2*DD];             // channel1 || channel2
__device__ __half g_n[(size_t)T2*DD];              // n1 || n2 (half)
__device__ __half g_key[(size_t)BB*DD*NN_TOK];     // [B,D,N] half
__device__ __half g_query[(size_t)T_TOK*DD];       // half
__device__ __half g_ctx[(size_t)BB*DD*DD];         // half (GEMM out+in)
__device__ __half g_att2[(size_t)T_TOK*DD];        // half
__device__ float  g_rep[(size_t)T_TOK*C2];
__device__ float  g_crossln[(size_t)T_TOK*C2];
__device__ float  g_tx[(size_t)T_TOK*C2];
__device__ float  g_h1[(size_t)T_TOK*C4];
__device__ __half g_h2[(size_t)T_TOK*C4];          // half (GEMM A)
// pre-converted / pre-transposed weights (half)
__device__ __half g_wqkv[(size_t)DD*1152];
__device__ __half g_wproj[(size_t)DD*DD];
__device__ __half g_wrpT[(size_t)DD*C2];
__device__ __half g_wfc1[(size_t)C2*C4];
__device__ __half g_wfc2[(size_t)C4*C2];

// ---------------- reductions -------------------------------------------------
__device__ __forceinline__ float warpSum(float v){
    #pragma unroll
    for(int o=16;o>0;o>>=1) v += __shfl_down_sync(0xffffffffu, v, o);
    return v;
}
__device__ __forceinline__ float warpMax(float v){
    #pragma unroll
    for(int o=16;o>0;o>>=1) v = fmaxf(v, __shfl_down_sync(0xffffffffu, v, o));
    return v;
}
__device__ __forceinline__ float blockSum(float v, float* sh){
    int lane = threadIdx.x & 31, wid = threadIdx.x >> 5;
    v = warpSum(v);
    if(lane==0) sh[wid]=v;
    __syncthreads();
    int nw = blockDim.x >> 5;
    float r = (threadIdx.x < (unsigned)nw) ? sh[threadIdx.x] : 0.f;
    if(wid==0){ r = warpSum(r); if(lane==0) sh[0]=r; }
    __syncthreads();
    r = sh[0];
    __syncthreads();
    return r;
}
__device__ __forceinline__ float blockMax(float v, float* sh){
    int lane = threadIdx.x & 31, wid = threadIdx.x >> 5;
    v = warpMax(v);
    if(lane==0) sh[wid]=v;
    __syncthreads();
    int nw = blockDim.x >> 5;
    float r = (threadIdx.x < (unsigned)nw) ? sh[threadIdx.x] : -INFINITY;
    if(wid==0){ r = warpMax(r); if(lane==0) sh[0]=r; }
    __syncthreads();
    r = sh[0];
    __syncthreads();
    return r;
}

// ---------------- mma / ldmatrix / cp.async helpers ---------------------------
__device__ __forceinline__ void mma_f16(float* c, const uint32_t* a, const uint32_t* b){
    asm volatile(
        "mma.sync.aligned.m16n8k16.row.col.f32.f16.f16.f32 "
        "{%0,%1,%2,%3}, {%4,%5,%6,%7}, {%8,%9}, {%0,%1,%2,%3};\n"
        : "+f"(c[0]), "+f"(c[1]), "+f"(c[2]), "+f"(c[3])
        : "r"(a[0]), "r"(a[1]), "r"(a[2]), "r"(a[3]),
          "r"(b[0]), "r"(b[1]));
}
__device__ __forceinline__ void ldsm4(uint32_t* r, uint32_t addr){
    asm volatile("ldmatrix.sync.aligned.m8n8.x4.shared.b16 {%0,%1,%2,%3}, [%4];\n"
                 : "=r"(r[0]), "=r"(r[1]), "=r"(r[2]), "=r"(r[3]) : "r"(addr));
}
__device__ __forceinline__ void ldsm4t(uint32_t* r, uint32_t addr){
    asm volatile("ldmatrix.sync.aligned.m8n8.x4.trans.shared.b16 {%0,%1,%2,%3}, [%4];\n"
                 : "=r"(r[0]), "=r"(r[1]), "=r"(r[2]), "=r"(r[3]) : "r"(addr));
}
__device__ __forceinline__ void cp16(uint32_t s, const void* g){
    asm volatile("cp.async.cg.shared.global [%0], [%1], 16;\n" :: "r"(s), "l"(g));
}
__device__ __forceinline__ void cp_commit(){ asm volatile("cp.async.commit_group;\n"); }
__device__ __forceinline__ void cp_wait2(){ asm volatile("cp.async.wait_group 2;\n"); }
__device__ __forceinline__ void cp_wait1(){ asm volatile("cp.async.wait_group 1;\n"); }
__device__ __forceinline__ void cp_wait0(){ asm volatile("cp.async.wait_group 0;\n"); }

__device__ __forceinline__ void storev(float* p, float v){ *p = v; }
__device__ __forceinline__ void storev(__half* p, float v){ *p = __float2half_rn(v); }

// ---------------- pack x1||x2 -------------------------------------------------
__global__ void pack_kernel(const float* __restrict__ x1, const float* __restrict__ x2,
                            float* __restrict__ x){
    long i = ((long)blockIdx.x*blockDim.x + threadIdx.x)*4;
    const long half_ = (long)T_TOK*DD;
    float4 v = (i < half_) ? *(const float4*)&x1[i] : *(const float4*)&x2[i-half_];
    *(float4*)&x[i] = v;
}

// ---------------- weight prep: convert 4 weight matrices to half --------------
#define NW1 (DD*1152)
#define NW2 (DD*DD)
#define NW3 (C2*C4)
#define NW4 (C4*C2)
__global__ void cvt4_kernel(const float* __restrict__ a, __half* __restrict__ oa,
                            const float* __restrict__ b, __half* __restrict__ ob,
                            const float* __restrict__ c, __half* __restrict__ oc,
                            const float* __restrict__ d, __half* __restrict__ od){
    int i = blockIdx.x*blockDim.x + threadIdx.x;
    if(i < NW1){ oa[i] = __float2half_rn(a[i]); return; }
    i -= NW1;
    if(i < NW2){ ob[i] = __float2half_rn(b[i]); return; }
    i -= NW2;
    if(i < NW3){ oc[i] = __float2half_rn(c[i]); return; }
    i -= NW3;
    if(i < NW4){ od[i] = __float2half_rn(d[i]); }
}
// rp_w [768][384] -> rpT [384][768], half
__global__ void transpose_cvt_kernel(const float* __restrict__ in, __half* __restrict__ out){
    __shared__ float t[32][33];
    int k0 = blockIdx.x*32, n0 = blockIdx.y*32;
    int tx = threadIdx.x, ty = threadIdx.y;   // 32 x 8
    #pragma unroll
    for(int j=0;j<4;j++) t[ty+8*j][tx] = in[(n0+ty+8*j)*DD + k0+tx];
    __syncthreads();
    #pragma unroll
    for(int j=0;j<4;j++) out[(k0+ty+8*j)*C2 + n0+tx] = __float2half_rn(t[tx][ty+8*j]);
}

// ---------------- LayerNorm (W = 384 or 768; block=128) ----------------------
template<typename OUT>
__global__ void ln_kernel(const float* __restrict__ x, const float* __restrict__ g,
                          const float* __restrict__ b, OUT* __restrict__ y, int W){
    long row = blockIdx.x;
    const float* xr = x + row*(long)W;
    int vpt = W >> 7;
    float v[6];
    float s=0.f, s2=0.f;
    for(int i=0;i<vpt;i++){
        float t = xr[i*128 + threadIdx.x];
        v[i]=t; s+=t; s2+=t*t;
    }
    __shared__ float sh[32];
    s  = blockSum(s, sh);
    s2 = blockSum(s2, sh);
    float mu = s / (float)W;
    float var = s2 / (float)W - mu*mu;
    float rstd = rsqrtf(var + 1e-5f);
    OUT* yr = y + row*(long)W;
    for(int i=0;i<vpt;i++){
        int c = i*128 + threadIdx.x;
        storev(&yr[c], (v[i]-mu)*rstd*g[c] + b[c]);
    }
}

// ---------------- fused: tx = concat(ch)+crossln; lnw = half(LN2(tx)) ---------
__global__ void tx_ln_kernel(const float* __restrict__ ch, const float* __restrict__ cl,
                             const float* __restrict__ g, const float* __restrict__ b,
                             float* __restrict__ tx, __half* __restrict__ y){
    long row = blockIdx.x;
    const float* clr = cl + row*C2;
    float v[6];
    float s=0.f, s2=0.f;
    #pragma unroll
    for(int i=0;i<6;i++){
        int c = i*128 + threadIdx.x;
        float base = (c < DD) ? ch[row*DD + c] : ch[((long)T_TOK + row)*DD + c - DD];
        float t = base + clr[c];
        v[i]=t; s+=t; s2+=t*t;
    }
    __shared__ float sh[32];
    s  = blockSum(s, sh);
    s2 = blockSum(s2, sh);
    float mu = s / (float)C2;
    float var = s2 / (float)C2 - mu*mu;
    float rstd = rsqrtf(var + 1e-5f);
    float* txr = tx + row*C2;
    __half* yr  = y + row*C2;
    #pragma unroll
    for(int i=0;i<6;i++){
        int c = i*128 + threadIdx.x;
        txr[c] = v[i];
        yr[c] = __float2half_rn((v[i]-mu)*rstd*g[c] + b[c]);
    }
}

// ---------------- L2-norm over tokens + transpose to [S,B,h,d,N] --------------
__global__ void l2norm_qk_kernel(const float* __restrict__ qkv,
                                 float* __restrict__ qn, float* __restrict__ kn){
    int idx = blockIdx.x;
    int stream = idx / (2*BB*HEADS*HD);
    int rest = idx % (2*BB*HEADS*HD);
    int which = rest / (BB*HEADS*HD);     // 0 = q, 1 = k
    int r = rest % (BB*HEADS*HD);
    int b = r / (HEADS*HD);
    int hj = r % (HEADS*HD);
    int col = which*DD + hj;
    const float* base = qkv + ((long)stream*T_TOK + (long)b*NN_TOK)*1152 + col;
    float v[4]; float s=0.f;
    #pragma unroll
    for(int i=0;i<4;i++){
        int n = threadIdx.x + i*256;
        float t = base[(long)n*1152];
        v[i]=t; s+=t*t;
    }
    __shared__ float sh[32];
    s = blockSum(s, sh);
    float nrm = sqrtf(s);
    float scale = 1.0f / fmaxf(nrm, 1e-12f);
    float* out = (which==0 ? qn : kn)
               + ((long)stream*BB*HEADS*HD + (long)b*(HEADS*HD) + hj)*NN_TOK;
    #pragma unroll
    for(int i=0;i<4;i++){
        int n = threadIdx.x + i*256;
        out[n] = v[i]*scale;
    }
}

// ---------------- attn logits: split-K partials (no atomics) ------------------
__global__ __launch_bounds__(256) void qk_kernel(const float* __restrict__ qn,
                                                 const float* __restrict__ kn,
                                                 float* __restrict__ attnp){
    int bh = blockIdx.y;
    int s = blockIdx.x;
    const float* q = qn + (long)bh*HD*NN_TOK;
    const float* k = kn + (long)bh*HD*NN_TOK;
    __shared__ float qs[48*65];
    __shared__ float ks[48*65];
    int tid = threadIdx.x;
    int tx = tid & 15, ty = tid >> 4;
    float acc[3][3];
    #pragma unroll
    for(int r=0;r<3;r++)
        #pragma unroll
        for(int c=0;c<3;c++) acc[r][c]=0.f;

    for(int sub=0; sub<2; sub++){
        int n0 = s*128 + sub*64;
        __syncthreads();
        #pragma unroll
        for(int i=0;i<12;i++){
            int e = tid + i*256;
            int rr = e>>6, cc = e&63;
            qs[rr*65+cc] = q[rr*NN_TOK + n0 + cc];
            ks[rr*65+cc] = k[rr*NN_TOK + n0 + cc];
        }
        __syncthreads();
        #pragma unroll 4
        for(int kk=0;kk<64;kk++){
            float qv[3], kv[3];
            #pragma unroll
            for(int r=0;r<3;r++) qv[r] = qs[(ty*3+r)*65 + kk];
            #pragma unroll
            for(int c=0;c<3;c++) kv[c] = ks[(tx*3+c)*65 + kk];
            #pragma unroll
            for(int r=0;r<3;r++)
                #pragma unroll
                for(int c=0;c<3;c++) acc[r][c] = fmaf(qv[r], kv[c], acc[r][c]);
        }
    }
    float* ab = attnp + ((long)s*(2*BB*HEADS) + bh)*2304;
    #pragma unroll
    for(int r=0;r<3;r++)
        #pragma unroll
        for(int c=0;c<3;c++)
            ab[(ty*3+r)*48 + tx*3+c] = acc[r][c];
}

// ---------------- softmax over last-48: reduce 8 partials, temp, softmax ------
__global__ void softmax_attn_kernel(const float* __restrict__ attnp,
                                    float* __restrict__ attn,
                                    const float* __restrict__ temp){
    int row = blockIdx.x;
    int bh = row / HD;
    int h = bh & (HEADS-1);
    float t = temp[h];
    int tid = threadIdx.x;
    float v = -INFINITY;
    if(tid < HD){
        float s = 0.f;
        #pragma unroll
        for(int p=0;p<8;p++)
            s += attnp[((long)p*(2*BB*HEADS) + bh)*2304 + (row % HD)*48 + tid];
        v = s * t;
    }
    __shared__ float sh[32];
    float m = blockMax(v, sh);
    float e = (tid<HD) ? expf(v - m) : 0.f;
    float s = blockSum(e, sh);
    if(tid<HD) attn[(long)row*HD + tid] = e / s;
}

// ---------------- attn @ v, chunked over tokens -------------------------------
__global__ __launch_bounds__(256) void pv_kernel(const float* __restrict__ attn,
                                                 const float* __restrict__ qkv,
                                                 __half* __restrict__ out){
    int bh2 = blockIdx.y;
    int n0 = blockIdx.x * 64;
    int stream = bh2 >> 7;
    int bh = bh2 & 127;
    int b = bh >> 3, h = bh & 7;
    long tokbase = (long)stream*T_TOK + (long)b*NN_TOK;
    __shared__ float as[48*49];
    __shared__ float vs[64*49];
    int tid = threadIdx.x;
    for(int i=tid;i<2304;i+=256){
        int r = i/48, c = i%48;
        as[r*49+c] = attn[(long)bh2*2304 + i];
    }
    const float* vbase = qkv + tokbase*1152 + 2*DD + h*HD;
    #pragma unroll
    for(int i=0;i<12;i++){
        int e = tid + i*256;
        int nn = e/48, j = e%48;
        vs[nn*49+j] = vbase[(long)(n0+nn)*1152 + j];
    }
    __syncthreads();
    int tx = tid & 15;
    int ty = tid >> 4;
    float acc[4][3];
    #pragma unroll
    for(int s=0;s<4;s++)
        #pragma unroll
        for(int r=0;r<3;r++) acc[s][r]=0.f;
    #pragma unroll 4
    for(int j=0;j<48;j++){
        float av[3], vv[4];
        #pragma unroll
        for(int r=0;r<3;r++) av[r] = as[(tx*3+r)*49 + j];
        #pragma unroll
        for(int s=0;s<4;s++) vv[s] = vs[(ty*4+s)*49 + j];
        #pragma unroll
        for(int s=0;s<4;s++)
            #pragma unroll
            for(int r=0;r<3;r++) acc[s][r] = fmaf(av[r], vv[s], acc[s][r]);
    }
    #pragma unroll
    for(int s=0;s<4;s++)
        #pragma unroll
        for(int r=0;r<3;r++)
            out[(tokbase + n0 + ty*4+s)*DD + h*HD + tx*3 + r] = __float2half_rn(acc[s][r]);
}

// ---------------- column softmax (over tokens) -> key half --------------------
__global__ void colsoftmax_kernel(const __half* __restrict__ x, __half* __restrict__ key){
    int idx = blockIdx.x;
    int b = idx / DD, d = idx % DD;
    const __half* base = x + (long)b*NN_TOK*DD + d;
    float v[4]; float m = -INFINITY;
    #pragma unroll
    for(int i=0;i<4;i++){
        int n = threadIdx.x + i*256;
        float t = __half2float(base[(long)n*DD]);
        v[i]=t; m = fmaxf(m,t);
    }
    __shared__ float sh[32];
    m = blockMax(m, sh);
    float s = 0.f;
    #pragma unroll
    for(int i=0;i<4;i++){ v[i] = expf(v[i]-m); s += v[i]; }
    s = blockSum(s, sh);
    float inv = 1.0f / s;
    __half* out = key + ((long)b*DD + d)*NN_TOK;
    #pragma unroll
    for(int i=0;i<4;i++) out[threadIdx.x + i*256] = __float2half_rn(v[i]*inv);
}

// ---------------- row softmax (over channels) -> query half -------------------
__global__ void rowsoftmax_kernel(const __half* __restrict__ x, __half* __restrict__ y){
    long row = blockIdx.x;
    const __half* xr = x + row*DD;
    float v[3]; float m = -INFINITY;
    #pragma unroll
    for(int i=0;i<3;i++){
        float t = __half2float(xr[i*128 + threadIdx.x]);
        v[i]=t; m=fmaxf(m,t);
    }
    __shared__ float sh[32];
    m = blockMax(m, sh);
    float s=0.f;
    #pragma unroll
    for(int i=0;i<3;i++){ v[i]=expf(v[i]-m); s+=v[i]; }
    s = blockSum(s, sh);
    float inv = 1.0f/s;
    __half* yr = y + row*DD;
    #pragma unroll
    for(int i=0;i<3;i++) yr[i*128 + threadIdx.x] = __float2half_rn(v[i]*inv);
}

// ---------------- depthwise 3x3 + exact GELU -> half --------------------------
__global__ void dwconv_gelu_kernel(const float* __restrict__ h1, const float* __restrict__ w,
                                   const float* __restrict__ bias, __half* __restrict__ h2){
    int c = blockIdx.x*blockDim.x + threadIdx.x;
    int y = blockIdx.y, b = blockIdx.z;
    const float* rowc = h1 + ((long)b*NN_TOK + y*32)*C4 + c;
    const float* rowm = rowc - 32*C4;
    const float* rowp = rowc + 32*C4;
    bool ym = (y > 0), yp = (y < 31);
    const float* wc = w + c*9;
    float w0=wc[0],w1=wc[1],w2=wc[2],w3=wc[3],w4=wc[4],w5=wc[5],w6=wc[6],w7=wc[7],w8=wc[8];
    float bs = bias[c];
    __half* outr = h2 + ((long)b*NN_TOK + y*32)*C4 + c;

    float pt=0.f, pm=0.f, pb=0.f;
    float ct = ym ? rowm[0] : 0.f;
    float cm = rowc[0];
    float cb = yp ? rowp[0] : 0.f;
    #pragma unroll 4
    for(int x=0;x<32;x++){
        float nt=0.f, nm=0.f, nb=0.f;
        if(x < 31){
            long o = (long)(x+1)*C4;
            nt = ym ? rowm[o] : 0.f;
            nm = rowc[o];
            nb = yp ? rowp[o] : 0.f;
        }
        float acc = bs;
        acc = fmaf(pt,w0,acc); acc = fmaf(ct,w1,acc); acc = fmaf(nt,w2,acc);
        acc = fmaf(pm,w3,acc); acc = fmaf(cm,w4,acc); acc = fmaf(nm,w5,acc);
        acc = fmaf(pb,w6,acc); acc = fmaf(cb,w7,acc); acc = fmaf(nb,w8,acc);
        float g = 0.5f*acc*(1.f + erff(acc*0.70710678118654752f));
        outr[(long)x*C4] = __float2half_rn(g);
        pt=ct; pm=cm; pb=cb; ct=nt; cm=nm; cb=nb;
    }
}

// ---------------- 3-stage cp.async fp16 GEMM (m16n8k16 + ldmatrix) ------------
// C = A@B (+bias)(+res); A,B half; C float or half (OUTH).
// 128x128x64 tile, 3 stages, 256 threads, warp tile 32x64.
// M%128==0, N%128==0, K%64==0, lda/ldb % 8 == 0.
#define ASTH 72                    // halfs per A row (64 + 8 pad); 144B, 16B-mult
#define BSTH 136                   // halfs per B row (128 + 8 pad); 272B
#define A_STAGEH (128*ASTH)        // 9216 halfs
#define B_STAGEH (64*BSTH)         // 8704 halfs
#define STAGEH (A_STAGEH + B_STAGEH)
#define SMEM_GEMM (3*STAGEH*2)     // 107520 bytes

template<bool BIAS, bool RES, bool OUTH>
__global__ __launch_bounds__(256,2)
void mma_gemm_kernel(const __half* __restrict__ A, const __half* __restrict__ Bm,
                     const float* __restrict__ bias, const float* __restrict__ res,
                     void* __restrict__ Cv,
                     int M, int N, int K, int lda, int ldb, int ldc,
                     long long sA, long long sB, long long sC){
    int bz = blockIdx.z;
    A  += (long long)bz*sA;
    Bm += (long long)bz*sB;
    float* Cf = (float*)Cv + (OUTH ? 0 : (long long)bz*sC);
    __half* Ch = (__half*)Cv + (OUTH ? (long long)bz*sC : 0);
    const float* R = RES ? res + (long long)bz*sC : nullptr;

    extern __shared__ __align__(16) __half hsm[];   // [3][STAGEH]

    const int rowT = blockIdx.y*128, colT = blockIdx.x*128;
    const int tid = threadIdx.x;
    const int warp = tid >> 5, lane = tid & 31;
    const int grp = lane >> 2, tg = lane & 3;
    const int warpRow = (warp & 3) * 32;
    const int warpCol = (warp >> 2) * 64;

    // cp.async coordinates: A 128 rows x 8 chunks(16B); B 64 rows x 16 chunks
    const int a_r = tid & 127, a_cb = (tid >> 7) * 4;   // 4 chunks each
    const int b_r = tid & 63,  b_cb = (tid >> 6) * 4;

    const int nIt = K >> 6;

    auto issue = [&](int it, int st){
        int k0 = it << 6;
        __half* Ad = hsm + st*STAGEH;
        __half* Bd = Ad + A_STAGEH;
        #pragma unroll
        for(int i=0;i<4;i++){
            int c8 = (a_cb + i) * 8;
            cp16((uint32_t)__cvta_generic_to_shared(&Ad[a_r*ASTH + c8]),
                 &A[(long)(rowT+a_r)*lda + k0 + c8]);
        }
        #pragma unroll
        for(int i=0;i<4;i++){
            int c8 = (b_cb + i) * 8;
            cp16((uint32_t)__cvta_generic_to_shared(&Bd[b_r*BSTH + c8]),
                 &Bm[(long)(k0+b_r)*ldb + colT + c8]);
        }
        cp_commit();
    };

    float acc[2][8][4];
    #pragma unroll
    for(int mi=0;mi<2;mi++)
        #pragma unroll
        for(int ni=0;ni<8;ni++)
            #pragma unroll
            for(int t=0;t<4;t++) acc[mi][ni][t]=0.f;

    issue(0, 0);
    if(nIt > 1) issue(1, 1);
    int st = 0;
    for(int it=0; it<nIt; it++){
        if(it+2 < nIt){
            int s2 = st+2; if(s2>=3) s2-=3;
            issue(it+2, s2);
            cp_wait2();
        } else if(it+1 < nIt){
            cp_wait1();
        } else {
            cp_wait0();
        }
        __syncthreads();
        const __half* Ac = hsm + st*STAGEH;
        const __half* Bc = Ac + A_STAGEH;
        uint32_t a_base = (uint32_t)__cvta_generic_to_shared(Ac);
        uint32_t b_base = (uint32_t)__cvta_generic_to_shared(Bc);
        #pragma unroll
        for(int kk=0;kk<4;kk++){
            uint32_t a[2][4], b[4][4];
            #pragma unroll
            for(int mi=0;mi<2;mi++){
                uint32_t addr = a_base +
                    ((warpRow + mi*16 + (lane & 15))*ASTH + kk*16 + (lane >> 4)*8)*2;
                ldsm4(a[mi], addr);
            }
            #pragma unroll
            for(int np=0;np<4;np++){
                uint32_t addr = b_base +
                    ((kk*16 + (lane & 15))*BSTH + warpCol + np*16 + (lane >> 4)*8)*2;
                ldsm4t(b[np], addr);
            }
            #pragma unroll
            for(int mi=0;mi<2;mi++)
                #pragma unroll
                for(int np=0;np<4;np++){
                    mma_f16(acc[mi][np*2+0], a[mi], &b[np][0]);
                    mma_f16(acc[mi][np*2+1], a[mi], &b[np][2]);
                }
        }
        __syncthreads();
        if(++st == 3) st = 0;
    }

    // epilogue
    #pragma unroll
    for(int mi=0;mi<2;mi++){
        #pragma unroll
        for(int ni=0;ni<8;ni++){
            int r0 = rowT + warpRow + mi*16 + grp;
            int col = colT + warpCol + ni*8 + tg*2;
            float2 o0, o1;
            o0.x = acc[mi][ni][0]; o0.y = acc[mi][ni][1];
            o1.x = acc[mi][ni][2]; o1.y = acc[mi][ni][3];
            if(BIAS){
                float b0 = bias[col], b1 = bias[col+1];
                o0.x += b0; o0.y += b1;
                o1.x += b0; o1.y += b1;
            }
            if(RES){
                const float2 r0v = *(const float2*)&R[(long)r0*ldc + col];
                const float2 r1v = *(const float2*)&R[(long)(r0+8)*ldc + col];
                o0.x += r0v.x; o0.y += r0v.y;
                o1.x += r1v.x; o1.y += r1v.y;
            }
            if(OUTH){
                __half2 h0 = __floats2half2_rn(o0.x, o0.y);
                __half2 h1 = __floats2half2_rn(o1.x, o1.y);
                *(__half2*)&Ch[(long)r0*ldc + col] = h0;
                *(__half2*)&Ch[(long)(r0+8)*ldc + col] = h1;
            }else{
                *(float2*)&Cf[(long)r0*ldc + col] = o0;
                *(float2*)&Cf[(long)(r0+8)*ldc + col] = o1;
            }
        }
    }
}

// ---------------- host side ---------------------------------------------------
static void* symaddr(const void* sym){
    void* p = nullptr;
    cudaGetSymbolAddress(&p, sym);
    return p;
}

extern "C" void kernel_launch(void* const* d_in, const int* in_sizes, int n_in,
                              void* d_out, int out_size){
    const float* x1       = (const float*)d_in[0];
    const float* x2       = (const float*)d_in[1];
    const float* ln1_g    = (const float*)d_in[2];
    const float* ln1_b    = (const float*)d_in[3];
    const float* ca_qkv_w = (const float*)d_in[4];
    const float* ca_temp  = (const float*)d_in[5];
    const float* ca_proj_w= (const float*)d_in[6];
    const float* ca_proj_b= (const float*)d_in[7];
    const float* ln3_g    = (const float*)d_in[8];
    const float* ln3_b    = (const float*)d_in[9];
    const float* rp_w     = (const float*)d_in[10];
    const float* rp_b     = (const float*)d_in[11];
    const float* cn_g     = (const float*)d_in[12];
    const float* cn_b     = (const float*)d_in[13];
    const float* ln2_g    = (const float*)d_in[14];
    const float* ln2_b    = (const float*)d_in[15];
    const float* fc1_w    = (const float*)d_in[16];
    const float* fc1_b    = (const float*)d_in[17];
    const float* dw_w     = (const float*)d_in[18];
    const float* dw_b     = (const float*)d_in[19];
    const float* fc2_w    = (const float*)d_in[20];
    const float* fc2_b    = (const float*)d_in[21];
    float* out = (float*)d_out;

    float*  p_x      = (float*) symaddr(g_x);
    __half* p_ln     = (__half*)symaddr(g_ln);
    __half* p_lnw    = (__half*)symaddr(g_lnw);
    float*  p_qkv    = (float*) symaddr(g_qkv);
    float*  p_qn     = (float*) symaddr(g_qn);
    float*  p_kn     = (float*) symaddr(g_kn);
    float*  p_attnp  = (float*) symaddr(g_attnp);
    float*  p_attn   = (float*) symaddr(g_attn);
    __half* p_attnout= (__half*)symaddr(g_attnout);
    float*  p_ch     = (float*) symaddr(g_ch);
    __half* p_n      = (__half*)symaddr(g_n);
    __half* p_key    = (__half*)symaddr(g_key);
    __half* p_query  = (__half*)symaddr(g_query);
    __half* p_ctx    = (__half*)symaddr(g_ctx);
    __half* p_att2   = (__half*)symaddr(g_att2);
    float*  p_rep    = (float*) symaddr(g_rep);
    float*  p_crossln= (float*) symaddr(g_crossln);
    float*  p_tx     = (float*) symaddr(g_tx);
    float*  p_h1     = (float*) symaddr(g_h1);
    __half* p_h2     = (__half*)symaddr(g_h2);
    __half* p_wqkv   = (__half*)symaddr(g_wqkv);
    __half* p_wproj  = (__half*)symaddr(g_wproj);
    __half* p_wrpT   = (__half*)symaddr(g_wrpT);
    __half* p_wfc1   = (__half*)symaddr(g_wfc1);
    __half* p_wfc2   = (__half*)symaddr(g_wfc2);

    cudaFuncSetAttribute(mma_gemm_kernel<false,false,false>, cudaFuncAttributeMaxDynamicSharedMemorySize, SMEM_GEMM);
    cudaFuncSetAttribute(mma_gemm_kernel<true ,true ,false>, cudaFuncAttributeMaxDynamicSharedMemorySize, SMEM_GEMM);
    cudaFuncSetAttribute(mma_gemm_kernel<false,false,true >, cudaFuncAttributeMaxDynamicSharedMemorySize, SMEM_GEMM);
    cudaFuncSetAttribute(mma_gemm_kernel<true ,false,false>, cudaFuncAttributeMaxDynamicSharedMemorySize, SMEM_GEMM);

    // ---- pack + weight prep ----
    pack_kernel<<<(T2*DD/4)/256, 256>>>(x1, x2, p_x);
    cvt4_kernel<<<(NW1+NW2+NW3+NW4+255)/256, 256>>>(
        ca_qkv_w, p_wqkv, ca_proj_w, p_wproj, fc1_w, p_wfc1, fc2_w, p_wfc2);
    transpose_cvt_kernel<<<dim3(DD/32, C2/32), dim3(32,8)>>>(rp_w, p_wrpT);

    // ---- channel attention, both streams batched ----
    ln_kernel<__half><<<T2, 128>>>(p_x, ln1_g, ln1_b, p_ln, DD);

    mma_gemm_kernel<false,false,false><<<dim3(1152/128, T2/128, 1), 256, SMEM_GEMM>>>(
        p_ln, p_wqkv, nullptr, nullptr, p_qkv,
        T2, 1152, DD, DD, 1152, 1152, 0, 0, 0);

    l2norm_qk_kernel<<<2*2*BB*HEADS*HD, 256>>>(p_qkv, p_qn, p_kn);
    qk_kernel<<<dim3(8, 2*BB*HEADS), 256>>>(p_qn, p_kn, p_attnp);
    softmax_attn_kernel<<<2*BB*HEADS*HD, 64>>>(p_attnp, p_attn, ca_temp);
    pv_kernel<<<dim3(16, 2*BB*HEADS), 256>>>(p_attn, p_qkv, p_attnout);

    mma_gemm_kernel<true,true,false><<<dim3(DD/128, T2/128, 1), 256, SMEM_GEMM>>>(
        p_attnout, p_wproj, ca_proj_b, p_x, p_ch,
        T2, DD, DD, DD, DD, DD, 0, 0, 0);

    // ---- ln3 (both streams) -> half ----
    ln_kernel<__half><<<T2, 128>>>(p_ch, ln3_g, ln3_b, p_n, DD);
    __half* p_n1 = p_n;
    __half* p_n2 = p_n + (size_t)T_TOK*DD;

    // ---- cross attention ----
    colsoftmax_kernel<<<BB*DD, 256>>>(p_n2, p_key);
    rowsoftmax_kernel<<<T_TOK, 128>>>(p_n2, p_query);

    // ctx[b] = key[b] (D x N) @ n1[b] (N x D) -> half
    mma_gemm_kernel<false,false,true><<<dim3(DD/128, DD/128, BB), 256, SMEM_GEMM>>>(
        p_key, p_n1, nullptr, nullptr, p_ctx,
        DD, DD, NN_TOK, NN_TOK, DD, DD,
        (long long)DD*NN_TOK, (long long)NN_TOK*DD, (long long)DD*DD);

    // att2[b] = query[b] (N x D) @ ctx[b] (D x D) -> half
    mma_gemm_kernel<false,false,true><<<dim3(DD/128, NN_TOK/128, BB), 256, SMEM_GEMM>>>(
        p_query, p_ctx, nullptr, nullptr, p_att2,
        NN_TOK, DD, DD, DD, DD, DD,
        (long long)NN_TOK*DD, (long long)DD*DD, (long long)NN_TOK*DD);

    // rep = att2 (T x 384) @ rpT (384 x 768) + rp_b -> float
    mma_gemm_kernel<true,false,false><<<dim3(C2/128, T_TOK/128, 1), 256, SMEM_GEMM>>>(
        p_att2, p_wrpT, rp_b, nullptr, p_rep,
        T_TOK, C2, DD, DD, C2, C2, 0, 0, 0);

    ln_kernel<float><<<T_TOK, 128>>>(p_rep, cn_g, cn_b, p_crossln, C2);

    // ---- fused tx = concat+cross, ln2 -> half ----
    tx_ln_kernel<<<T_TOK, 128>>>(p_ch, p_crossln, ln2_g, ln2_b, p_tx, p_lnw);

    // ---- MixFFN ----
    mma_gemm_kernel<true,false,false><<<dim3(C4/128, T_TOK/128, 1), 256, SMEM_GEMM>>>(
        p_lnw, p_wfc1, fc1_b, nullptr, p_h1,
        T_TOK, C4, C2, C2, C4, C4, 0, 0, 0);

    dwconv_gelu_kernel<<<dim3(C4/256, 32, BB), 256>>>(p_h1, dw_w, dw_b, p_h2);

    mma_gemm_kernel<true,true,false><<<dim3(C2/128, T_TOK/128, 1), 256, SMEM_GEMM>>>(
        p_h2, p_wfc2, fc2_b, p_tx, out,
        T_TOK, C2, C4, C4, C2, C2, 0, 0, 0);
}